// round 1
// baseline (speedup 1.0000x reference)
#include <cuda_runtime.h>
#include <cstdint>

#define NN      200000
#define EE      1200000
#define INDIM   128
#define HID     64
#define GG      1024
#define NCLS    6
#define LAYERS  3
#define BN_EPS  1e-5f

// ---------------- scratch (static device globals; no allocation) ----------------
__device__ float g_h  [(size_t)NN * HID];   // node features (51.2 MB)
__device__ float g_agg[(size_t)NN * HID];   // neighbor aggregation
__device__ float g_z  [(size_t)NN * HID];   // MLP intermediate
__device__ float g_pool[GG * HID];          // per-graph sums
__device__ int   g_cnt [GG];                // per-graph node counts

// ---------------- zero kernels ----------------
__global__ void zero_agg_kernel() {
    int i = blockIdx.x * blockDim.x + threadIdx.x;
    if (i < NN * HID / 4)
        reinterpret_cast<float4*>(g_agg)[i] = make_float4(0.f, 0.f, 0.f, 0.f);
}

__global__ void zero_pool_kernel() {
    int i = blockIdx.x * blockDim.x + threadIdx.x;
    if (i < GG * HID) g_pool[i] = 0.f;
    if (i < GG)       g_cnt[i]  = 0;
}

// ---------------- fused GEMM(+optional add) + BN + ReLU ----------------
// tile: 64 nodes x 64 outs, K-chunks of 32. 64 threads: og = t&7 (outs og+8j),
// ng = t>>3 (nodes ng*8+i). acc[8][8] per thread. All inner LDS conflict-free.
template<int K, bool ADD>
__global__ void __launch_bounds__(64)
gemm_bn_relu(const float* __restrict__ in, const float* __restrict__ addm,
             const float* __restrict__ W,  const float* __restrict__ bias,
             const float* __restrict__ bg, const float* __restrict__ bb,
             const float* __restrict__ bm, const float* __restrict__ bv,
             float* __restrict__ out)
{
    __shared__ float xs[64][33];   // [node][k-chunk], pad to kill bank conflicts
    __shared__ float Wsm[32][64];  // [k-chunk][out]

    const int t   = threadIdx.x;
    const int og  = t & 7;
    const int ng  = t >> 3;
    const int n0  = blockIdx.x * 64;

    float acc[8][8];
#pragma unroll
    for (int i = 0; i < 8; i++)
#pragma unroll
        for (int j = 0; j < 8; j++) acc[i][j] = 0.f;

    for (int k0 = 0; k0 < K; k0 += 32) {
        // fill xs: 64 rows x 32 k  (coalesced: consecutive t -> consecutive kk)
#pragma unroll 4
        for (int r = 0; r < 32; r++) {
            int i  = r * 64 + t;
            int nn = i >> 5, kk = i & 31;
            size_t gi = (size_t)(n0 + nn) * K + k0 + kk;
            float val = in[gi];
            if (ADD) val += addm[gi];
            xs[nn][kk] = val;
        }
        // fill W chunk: 32 x 64 (coalesced)
#pragma unroll 4
        for (int r = 0; r < 32; r++) {
            int i  = r * 64 + t;
            int kk = i >> 6, oo = i & 63;
            Wsm[kk][oo] = W[(size_t)(k0 + kk) * HID + oo];
        }
        __syncthreads();

#pragma unroll 8
        for (int kk = 0; kk < 32; kk++) {
            float xv[8], wv[8];
#pragma unroll
            for (int i = 0; i < 8; i++) xv[i] = xs[ng * 8 + i][kk];
#pragma unroll
            for (int j = 0; j < 8; j++) wv[j] = Wsm[kk][og + 8 * j];
#pragma unroll
            for (int i = 0; i < 8; i++)
#pragma unroll
                for (int j = 0; j < 8; j++) acc[i][j] += xv[i] * wv[j];
        }
        __syncthreads();
    }

    // epilogue: y = relu((dot + bias - m) * g*rsqrt(v+eps) + b)
#pragma unroll
    for (int j = 0; j < 8; j++) {
        int o    = og + 8 * j;
        float s  = bg[o] * rsqrtf(bv[o] + BN_EPS);
        float sh = (bias[o] - bm[o]) * s + bb[o];
#pragma unroll
        for (int i = 0; i < 8; i++) {
            int node = n0 + ng * 8 + i;
            float y  = acc[i][j] * s + sh;
            out[(size_t)node * HID + o] = fmaxf(y, 0.f);
        }
    }
}

// ---------------- edge scatter: agg[dst] += h[src] ----------------
// one thread per (edge, 16B chunk): 16 threads/edge, vector reduction to L2.
__global__ void scatter_kernel(const int* __restrict__ src,
                               const int* __restrict__ dst)
{
    int idx = blockIdx.x * blockDim.x + threadIdx.x;
    int e = idx >> 4;
    if (e >= EE) return;
    int c = idx & 15;
    int s = __ldg(src + e);
    int d = __ldg(dst + e);
    const float4 v = *reinterpret_cast<const float4*>(g_h + (size_t)s * HID + c * 4);
    float4* p = reinterpret_cast<float4*>(g_agg + (size_t)d * HID + c * 4);
    asm volatile("red.global.add.v4.f32 [%0], {%1,%2,%3,%4};"
                 :: "l"(p), "f"(v.x), "f"(v.y), "f"(v.z), "f"(v.w)
                 : "memory");
}

// ---------------- per-graph pooling (sum + count) ----------------
__global__ void pool_kernel(const int* __restrict__ batch)
{
    int idx = blockIdx.x * blockDim.x + threadIdx.x;
    int node = idx >> 4;
    if (node >= NN) return;
    int c = idx & 15;
    int b = __ldg(batch + node);
    const float4 v = *reinterpret_cast<const float4*>(g_h + (size_t)node * HID + c * 4);
    float4* p = reinterpret_cast<float4*>(g_pool + b * HID + c * 4);
    asm volatile("red.global.add.v4.f32 [%0], {%1,%2,%3,%4};"
                 :: "l"(p), "f"(v.x), "f"(v.y), "f"(v.z), "f"(v.w)
                 : "memory");
    if (c == 0) atomicAdd(&g_cnt[b], 1);
}

// ---------------- classifier head ----------------
__global__ void classifier_kernel(const float* __restrict__ W1, const float* __restrict__ b1,
                                  const float* __restrict__ W2, const float* __restrict__ b2,
                                  float* __restrict__ out)
{
    __shared__ float W1s[64 * 32];
    __shared__ float W2s[32 * NCLS];
    __shared__ float b1s[32];
    __shared__ float b2s[NCLS];
    int t = threadIdx.x;
    for (int i = t; i < 64 * 32;   i += 256) W1s[i] = W1[i];
    for (int i = t; i < 32 * NCLS; i += 256) W2s[i] = W2[i];
    if (t < 32)   b1s[t] = b1[t];
    if (t < NCLS) b2s[t] = b2[t];
    __syncthreads();

    int g = blockIdx.x * 256 + t;
    if (g >= GG) return;
    float inv = 1.f / fmaxf((float)g_cnt[g], 1.f);

    float h1[32];
#pragma unroll
    for (int j = 0; j < 32; j++) h1[j] = b1s[j];
    for (int k = 0; k < HID; k++) {
        float p = g_pool[g * HID + k] * inv;
#pragma unroll
        for (int j = 0; j < 32; j++) h1[j] += p * W1s[k * 32 + j];
    }
#pragma unroll
    for (int j = 0; j < 32; j++) h1[j] = fmaxf(h1[j], 0.f);

#pragma unroll
    for (int c = 0; c < NCLS; c++) {
        float o = b2s[c];
#pragma unroll
        for (int j = 0; j < 32; j++) o += h1[j] * W2s[j * NCLS + c];
        out[g * NCLS + c] = o;
    }
}

// ---------------- launcher ----------------
extern "C" void kernel_launch(void* const* d_in, const int* in_sizes, int n_in,
                              void* d_out, int out_size)
{
    const float* x      = (const float*)d_in[0];
    const int*   ei     = (const int*)  d_in[1];
    const int*   batch  = (const int*)  d_in[2];
    const float* emb_w  = (const float*)d_in[3];
    const float* emb_b  = (const float*)d_in[4];
    const float* ibn_g  = (const float*)d_in[5];
    const float* ibn_b  = (const float*)d_in[6];
    const float* ibn_m  = (const float*)d_in[7];
    const float* ibn_v  = (const float*)d_in[8];
    const float* fc1_w  = (const float*)d_in[9];
    const float* fc1_b  = (const float*)d_in[10];
    const float* mbn_g  = (const float*)d_in[11];
    const float* mbn_b  = (const float*)d_in[12];
    const float* mbn_m  = (const float*)d_in[13];
    const float* mbn_v  = (const float*)d_in[14];
    const float* fc2_w  = (const float*)d_in[15];
    const float* fc2_b  = (const float*)d_in[16];
    const float* obn_g  = (const float*)d_in[17];
    const float* obn_b  = (const float*)d_in[18];
    const float* obn_m  = (const float*)d_in[19];
    const float* obn_v  = (const float*)d_in[20];
    const float* cls1_w = (const float*)d_in[21];
    const float* cls1_b = (const float*)d_in[22];
    const float* cls2_w = (const float*)d_in[23];
    const float* cls2_b = (const float*)d_in[24];
    float* out = (float*)d_out;

    const int* src = ei;        // edge_index[0]
    const int* dst = ei + EE;   // edge_index[1]

    float *hp, *ap, *zp;
    cudaGetSymbolAddress((void**)&hp, g_h);
    cudaGetSymbolAddress((void**)&ap, g_agg);
    cudaGetSymbolAddress((void**)&zp, g_z);

    const int NB = NN / 64;  // 3125 node-tiles

    // input embedding -> BN -> relu
    gemm_bn_relu<INDIM, false><<<NB, 64>>>(x, nullptr, emb_w, emb_b,
                                           ibn_g, ibn_b, ibn_m, ibn_v, hp);

    for (int l = 0; l < LAYERS; l++) {
        zero_agg_kernel<<<(NN * HID / 4 + 255) / 256, 256>>>();
        scatter_kernel<<<(EE * 16 + 255) / 256, 256>>>(src, dst);
        // z = relu(bn1(fc1 @ (h + agg) + b1))
        gemm_bn_relu<HID, true><<<NB, 64>>>(
            hp, ap,
            fc1_w + (size_t)l * HID * HID, fc1_b + l * HID,
            mbn_g + l * HID, mbn_b + l * HID, mbn_m + l * HID, mbn_v + l * HID,
            zp);
        // h = relu(bn2(fc2 @ z + b2))
        gemm_bn_relu<HID, false><<<NB, 64>>>(
            zp, nullptr,
            fc2_w + (size_t)l * HID * HID, fc2_b + l * HID,
            obn_g + l * HID, obn_b + l * HID, obn_m + l * HID, obn_v + l * HID,
            hp);
    }

    zero_pool_kernel<<<(GG * HID + 255) / 256, 256>>>();
    pool_kernel<<<(NN * 16 + 255) / 256, 256>>>(batch);
    classifier_kernel<<<(GG + 255) / 256, 256>>>(cls1_w, cls1_b, cls2_w, cls2_b, out);
}

// round 2
// speedup vs baseline: 1.3339x; 1.3339x over previous
#include <cuda_runtime.h>
#include <cstdint>

#define NN      200000
#define EE      1200000
#define INDIM   128
#define HID     64
#define GG      1024
#define NCLS    6
#define LAYERS  3
#define BN_EPS  1e-5f

// ---------------- scratch (static device globals; no allocation) ----------------
__device__ float g_h  [(size_t)NN * HID];   // node features (51.2 MB)
__device__ float g_agg[(size_t)NN * HID];   // aggregation buffer (init'd to h by producers)
__device__ float g_pool[GG * HID];          // per-graph sums
__device__ int   g_cnt [GG];                // per-graph node counts

__global__ void zero_pool_kernel() {
    int i = blockIdx.x * blockDim.x + threadIdx.x;
    if (i < GG * HID) g_pool[i] = 0.f;
    if (i < GG)       g_cnt[i]  = 0;
}

// ============================================================================
// Shared GEMM micro-structure:
//   tile = 128 nodes x 64 outs, 256 threads
//   og = t & 15  -> outs  og*4 + j (j<4, contiguous -> LDS.128 / STG.128)
//   ng = t >> 4  -> nodes ng*8 + i (i<8, contiguous -> 2x LDS.128)
//   per-thread acc[8][4]; inner loop: 3x LDS.128 per 32 FMA.
//   xs is [k][node] with row stride 132 floats (16B aligned, mild STS conflicts
//   on the transpose store only).
// ============================================================================

#define XPAD 132

// ---------------- embed: x @ emb_w -> BN -> relu -> write h AND agg ----------
__global__ void __launch_bounds__(256, 4)
embed_kernel(const float* __restrict__ x,  const float* __restrict__ W,
             const float* __restrict__ bias,
             const float* __restrict__ bg, const float* __restrict__ bb,
             const float* __restrict__ bm, const float* __restrict__ bv,
             float* __restrict__ outh, float* __restrict__ outa)
{
    __shared__ float xs[32][XPAD];
    __shared__ float Wsm[32][64];

    const int t  = threadIdx.x;
    const int og = t & 15;
    const int ng = t >> 4;
    const int n0 = blockIdx.x * 128;

    float acc[8][4];
#pragma unroll
    for (int i = 0; i < 8; i++)
#pragma unroll
        for (int j = 0; j < 4; j++) acc[i][j] = 0.f;

    for (int k0 = 0; k0 < INDIM; k0 += 32) {
#pragma unroll
        for (int r = 0; r < 4; r++) {               // stage x chunk (transposed)
            int idx = r * 256 + t;
            int nn = idx >> 3, kq = idx & 7;
            int node = min(n0 + nn, NN - 1);
            float4 v = *reinterpret_cast<const float4*>(x + (size_t)node * INDIM + k0 + kq * 4);
            xs[kq * 4 + 0][nn] = v.x; xs[kq * 4 + 1][nn] = v.y;
            xs[kq * 4 + 2][nn] = v.z; xs[kq * 4 + 3][nn] = v.w;
        }
#pragma unroll
        for (int r = 0; r < 8; r++) {               // stage W chunk
            int i = r * 256 + t;
            int kk = i >> 6, oo = i & 63;
            Wsm[kk][oo] = W[(size_t)(k0 + kk) * HID + oo];
        }
        __syncthreads();
#pragma unroll 8
        for (int kk = 0; kk < 32; kk++) {
            float4 xa = *reinterpret_cast<const float4*>(&xs[kk][ng * 8]);
            float4 xb = *reinterpret_cast<const float4*>(&xs[kk][ng * 8 + 4]);
            float4 w  = *reinterpret_cast<const float4*>(&Wsm[kk][og * 4]);
            float xv[8] = {xa.x, xa.y, xa.z, xa.w, xb.x, xb.y, xb.z, xb.w};
            float wv[4] = {w.x, w.y, w.z, w.w};
#pragma unroll
            for (int i = 0; i < 8; i++)
#pragma unroll
                for (int j = 0; j < 4; j++) acc[i][j] += xv[i] * wv[j];
        }
        __syncthreads();
    }

    // epilogue: BN + relu, write h and agg (vectorized, coalesced)
    float s[4], sh[4];
#pragma unroll
    for (int j = 0; j < 4; j++) {
        int o = og * 4 + j;
        s[j]  = __ldg(bg + o) * rsqrtf(__ldg(bv + o) + BN_EPS);
        sh[j] = (__ldg(bias + o) - __ldg(bm + o)) * s[j] + __ldg(bb + o);
    }
#pragma unroll
    for (int i = 0; i < 8; i++) {
        int node = n0 + ng * 8 + i;
        if (node < NN) {
            float4 v;
            v.x = fmaxf(acc[i][0] * s[0] + sh[0], 0.f);
            v.y = fmaxf(acc[i][1] * s[1] + sh[1], 0.f);
            v.z = fmaxf(acc[i][2] * s[2] + sh[2], 0.f);
            v.w = fmaxf(acc[i][3] * s[3] + sh[3], 0.f);
            *reinterpret_cast<float4*>(outh + (size_t)node * HID + og * 4) = v;
            *reinterpret_cast<float4*>(outa + (size_t)node * HID + og * 4) = v;
        }
    }
}

// ---------------- fused GIN MLP: (h+agg) -> fc1,bn,relu -> fc2,bn,relu ------
// input = g_agg (already h + neighbor sum); z tile stays in smem.
__global__ void __launch_bounds__(256, 3)
fused_mlp(const float* __restrict__ in,
          const float* __restrict__ W1, const float* __restrict__ b1,
          const float* __restrict__ g1, const float* __restrict__ bb1,
          const float* __restrict__ m1, const float* __restrict__ v1,
          const float* __restrict__ W2, const float* __restrict__ b2,
          const float* __restrict__ g2, const float* __restrict__ bb2,
          const float* __restrict__ m2, const float* __restrict__ v2,
          float* __restrict__ outh, float* __restrict__ outa)
{
    __shared__ float xs[32][XPAD];
    __shared__ float zs[64][XPAD];
    __shared__ float Wsm[32][64];

    const int t  = threadIdx.x;
    const int og = t & 15;
    const int ng = t >> 4;
    const int n0 = blockIdx.x * 128;

    float acc[8][4];
#pragma unroll
    for (int i = 0; i < 8; i++)
#pragma unroll
        for (int j = 0; j < 4; j++) acc[i][j] = 0.f;

    // ---------- GEMM1: z = (h+agg) @ W1 ----------
    for (int k0 = 0; k0 < HID; k0 += 32) {
#pragma unroll
        for (int r = 0; r < 4; r++) {
            int idx = r * 256 + t;
            int nn = idx >> 3, kq = idx & 7;
            int node = min(n0 + nn, NN - 1);
            float4 v = *reinterpret_cast<const float4*>(in + (size_t)node * HID + k0 + kq * 4);
            xs[kq * 4 + 0][nn] = v.x; xs[kq * 4 + 1][nn] = v.y;
            xs[kq * 4 + 2][nn] = v.z; xs[kq * 4 + 3][nn] = v.w;
        }
#pragma unroll
        for (int r = 0; r < 8; r++) {
            int i = r * 256 + t;
            int kk = i >> 6, oo = i & 63;
            Wsm[kk][oo] = W1[(size_t)(k0 + kk) * HID + oo];
        }
        __syncthreads();
#pragma unroll 8
        for (int kk = 0; kk < 32; kk++) {
            float4 xa = *reinterpret_cast<const float4*>(&xs[kk][ng * 8]);
            float4 xb = *reinterpret_cast<const float4*>(&xs[kk][ng * 8 + 4]);
            float4 w  = *reinterpret_cast<const float4*>(&Wsm[kk][og * 4]);
            float xv[8] = {xa.x, xa.y, xa.z, xa.w, xb.x, xb.y, xb.z, xb.w};
            float wv[4] = {w.x, w.y, w.z, w.w};
#pragma unroll
            for (int i = 0; i < 8; i++)
#pragma unroll
                for (int j = 0; j < 4; j++) acc[i][j] += xv[i] * wv[j];
        }
        __syncthreads();
    }

    // epilogue1: BN + relu -> zs ([k][node] layout for GEMM2)
    {
        float s[4], sh[4];
#pragma unroll
        for (int j = 0; j < 4; j++) {
            int o = og * 4 + j;
            s[j]  = __ldg(g1 + o) * rsqrtf(__ldg(v1 + o) + BN_EPS);
            sh[j] = (__ldg(b1 + o) - __ldg(m1 + o)) * s[j] + __ldg(bb1 + o);
        }
#pragma unroll
        for (int i = 0; i < 8; i++)
#pragma unroll
            for (int j = 0; j < 4; j++)
                zs[og * 4 + j][ng * 8 + i] = fmaxf(acc[i][j] * s[j] + sh[j], 0.f);
    }
    __syncthreads();

    // ---------- GEMM2: h = z @ W2 ----------
#pragma unroll
    for (int i = 0; i < 8; i++)
#pragma unroll
        for (int j = 0; j < 4; j++) acc[i][j] = 0.f;

    for (int c = 0; c < 2; c++) {
#pragma unroll
        for (int r = 0; r < 8; r++) {
            int i = r * 256 + t;
            int kk = i >> 6, oo = i & 63;
            Wsm[kk][oo] = W2[(size_t)(c * 32 + kk) * HID + oo];
        }
        __syncthreads();
#pragma unroll 8
        for (int kk = 0; kk < 32; kk++) {
            float4 xa = *reinterpret_cast<const float4*>(&zs[c * 32 + kk][ng * 8]);
            float4 xb = *reinterpret_cast<const float4*>(&zs[c * 32 + kk][ng * 8 + 4]);
            float4 w  = *reinterpret_cast<const float4*>(&Wsm[kk][og * 4]);
            float xv[8] = {xa.x, xa.y, xa.z, xa.w, xb.x, xb.y, xb.z, xb.w};
            float wv[4] = {w.x, w.y, w.z, w.w};
#pragma unroll
            for (int i = 0; i < 8; i++)
#pragma unroll
                for (int j = 0; j < 4; j++) acc[i][j] += xv[i] * wv[j];
        }
        __syncthreads();
    }

    // epilogue2: BN + relu -> write h and agg
    float s[4], sh[4];
#pragma unroll
    for (int j = 0; j < 4; j++) {
        int o = og * 4 + j;
        s[j]  = __ldg(g2 + o) * rsqrtf(__ldg(v2 + o) + BN_EPS);
        sh[j] = (__ldg(b2 + o) - __ldg(m2 + o)) * s[j] + __ldg(bb2 + o);
    }
#pragma unroll
    for (int i = 0; i < 8; i++) {
        int node = n0 + ng * 8 + i;
        if (node < NN) {
            float4 v;
            v.x = fmaxf(acc[i][0] * s[0] + sh[0], 0.f);
            v.y = fmaxf(acc[i][1] * s[1] + sh[1], 0.f);
            v.z = fmaxf(acc[i][2] * s[2] + sh[2], 0.f);
            v.w = fmaxf(acc[i][3] * s[3] + sh[3], 0.f);
            *reinterpret_cast<float4*>(outh + (size_t)node * HID + og * 4) = v;
            *reinterpret_cast<float4*>(outa + (size_t)node * HID + og * 4) = v;
        }
    }
}

// ---------------- edge scatter: agg[dst] += h[src] ----------------
__global__ void scatter_kernel(const int* __restrict__ src,
                               const int* __restrict__ dst)
{
    int idx = blockIdx.x * blockDim.x + threadIdx.x;
    int e = idx >> 4;
    if (e >= EE) return;
    int c = idx & 15;
    int s = __ldg(src + e);
    int d = __ldg(dst + e);
    const float4 v = *reinterpret_cast<const float4*>(g_h + (size_t)s * HID + c * 4);
    float4* p = reinterpret_cast<float4*>(g_agg + (size_t)d * HID + c * 4);
    asm volatile("red.global.add.v4.f32 [%0], {%1,%2,%3,%4};"
                 :: "l"(p), "f"(v.x), "f"(v.y), "f"(v.z), "f"(v.w)
                 : "memory");
}

// ---------------- per-graph pooling (sum + count) ----------------
__global__ void pool_kernel(const int* __restrict__ batch)
{
    int idx = blockIdx.x * blockDim.x + threadIdx.x;
    int node = idx >> 4;
    if (node >= NN) return;
    int c = idx & 15;
    int b = __ldg(batch + node);
    const float4 v = *reinterpret_cast<const float4*>(g_h + (size_t)node * HID + c * 4);
    float4* p = reinterpret_cast<float4*>(g_pool + b * HID + c * 4);
    asm volatile("red.global.add.v4.f32 [%0], {%1,%2,%3,%4};"
                 :: "l"(p), "f"(v.x), "f"(v.y), "f"(v.z), "f"(v.w)
                 : "memory");
    if (c == 0) atomicAdd(&g_cnt[b], 1);
}

// ---------------- classifier head ----------------
__global__ void classifier_kernel(const float* __restrict__ W1, const float* __restrict__ b1,
                                  const float* __restrict__ W2, const float* __restrict__ b2,
                                  float* __restrict__ out)
{
    __shared__ float W1s[64 * 32];
    __shared__ float W2s[32 * NCLS];
    __shared__ float b1s[32];
    __shared__ float b2s[NCLS];
    int t = threadIdx.x;
    for (int i = t; i < 64 * 32;   i += 256) W1s[i] = W1[i];
    for (int i = t; i < 32 * NCLS; i += 256) W2s[i] = W2[i];
    if (t < 32)   b1s[t] = b1[t];
    if (t < NCLS) b2s[t] = b2[t];
    __syncthreads();

    int g = blockIdx.x * 256 + t;
    if (g >= GG) return;
    float inv = 1.f / fmaxf((float)g_cnt[g], 1.f);

    float h1[32];
#pragma unroll
    for (int j = 0; j < 32; j++) h1[j] = b1s[j];
    for (int k = 0; k < HID; k++) {
        float p = g_pool[g * HID + k] * inv;
#pragma unroll
        for (int j = 0; j < 32; j++) h1[j] += p * W1s[k * 32 + j];
    }
#pragma unroll
    for (int j = 0; j < 32; j++) h1[j] = fmaxf(h1[j], 0.f);

#pragma unroll
    for (int c = 0; c < NCLS; c++) {
        float o = b2s[c];
#pragma unroll
        for (int j = 0; j < 32; j++) o += h1[j] * W2s[j * NCLS + c];
        out[g * NCLS + c] = o;
    }
}

// ---------------- launcher ----------------
extern "C" void kernel_launch(void* const* d_in, const int* in_sizes, int n_in,
                              void* d_out, int out_size)
{
    const float* x      = (const float*)d_in[0];
    const int*   ei     = (const int*)  d_in[1];
    const int*   batch  = (const int*)  d_in[2];
    const float* emb_w  = (const float*)d_in[3];
    const float* emb_b  = (const float*)d_in[4];
    const float* ibn_g  = (const float*)d_in[5];
    const float* ibn_b  = (const float*)d_in[6];
    const float* ibn_m  = (const float*)d_in[7];
    const float* ibn_v  = (const float*)d_in[8];
    const float* fc1_w  = (const float*)d_in[9];
    const float* fc1_b  = (const float*)d_in[10];
    const float* mbn_g  = (const float*)d_in[11];
    const float* mbn_b  = (const float*)d_in[12];
    const float* mbn_m  = (const float*)d_in[13];
    const float* mbn_v  = (const float*)d_in[14];
    const float* fc2_w  = (const float*)d_in[15];
    const float* fc2_b  = (const float*)d_in[16];
    const float* obn_g  = (const float*)d_in[17];
    const float* obn_b  = (const float*)d_in[18];
    const float* obn_m  = (const float*)d_in[19];
    const float* obn_v  = (const float*)d_in[20];
    const float* cls1_w = (const float*)d_in[21];
    const float* cls1_b = (const float*)d_in[22];
    const float* cls2_w = (const float*)d_in[23];
    const float* cls2_b = (const float*)d_in[24];
    float* out = (float*)d_out;

    const int* src = ei;        // edge_index[0]
    const int* dst = ei + EE;   // edge_index[1]

    float *hp, *ap;
    cudaGetSymbolAddress((void**)&hp, g_h);
    cudaGetSymbolAddress((void**)&ap, g_agg);

    const int NB = (NN + 127) / 128;  // 1563 node-tiles

    // input embedding -> BN -> relu -> h, agg=h
    embed_kernel<<<NB, 256>>>(x, emb_w, emb_b, ibn_g, ibn_b, ibn_m, ibn_v, hp, ap);

    for (int l = 0; l < LAYERS; l++) {
        // agg += neighbor sum (agg already = h)
        scatter_kernel<<<(EE * 16 + 255) / 256, 256>>>(src, dst);
        // h = relu(bn2(fc2(relu(bn1(fc1(agg)))))) ; agg = h
        fused_mlp<<<NB, 256>>>(
            ap,
            fc1_w + (size_t)l * HID * HID, fc1_b + l * HID,
            mbn_g + l * HID, mbn_b + l * HID, mbn_m + l * HID, mbn_v + l * HID,
            fc2_w + (size_t)l * HID * HID, fc2_b + l * HID,
            obn_g + l * HID, obn_b + l * HID, obn_m + l * HID, obn_v + l * HID,
            hp, ap);
    }

    zero_pool_kernel<<<(GG * HID + 255) / 256, 256>>>();
    pool_kernel<<<(NN * 16 + 255) / 256, 256>>>(batch);
    classifier_kernel<<<(GG + 255) / 256, 256>>>(cls1_w, cls1_b, cls2_w, cls2_b, out);
}

// round 4
// speedup vs baseline: 1.6039x; 1.2024x over previous
#include <cuda_runtime.h>
#include <cstdint>

#define NN      200000
#define EE      1200000
#define INDIM   128
#define HID     64
#define GG      1024
#define NCLS    6
#define LAYERS  3
#define BN_EPS  1e-5f
#define NBLK    ((NN + 1023) / 1024)   // 196 scan blocks

// ---------------- scratch (static device globals; no allocation) ----------------
__device__ float g_h  [(size_t)NN * HID];
__device__ float g_agg[(size_t)NN * HID];
__device__ float g_pool[GG * HID];
__device__ int   g_cnt [GG];
// CSR structures (rebuilt every launch; deterministic given inputs)
__device__ int   g_rowptr[NN + 1];
__device__ int   g_cursor[NN];
__device__ int   g_colidx[EE];
__device__ int   g_bsum[256];
__device__ int   g_boff[256];

// ================= CSR build =================
__global__ void csr_zero_kernel() {
    int i = blockIdx.x * blockDim.x + threadIdx.x;
    if (i < NN) g_cursor[i] = 0;
}

__global__ void csr_hist_kernel(const int* __restrict__ dst) {
    int e = blockIdx.x * blockDim.x + threadIdx.x;
    if (e < EE) atomicAdd(&g_cursor[__ldg(dst + e)], 1);
}

// block-level exclusive scan: 1024 elems/block (256 thr x 4)
__global__ void csr_scan1_kernel() {
    __shared__ int wsum[8];
    int t = threadIdx.x, blk = blockIdx.x;
    int lane = t & 31, w = t >> 5;
    int base = blk * 1024 + t * 4;
    int c[4], s = 0;
#pragma unroll
    for (int k = 0; k < 4; k++) {
        c[k] = (base + k < NN) ? g_cursor[base + k] : 0;
        s += c[k];
    }
    int inc = s;
#pragma unroll
    for (int o = 1; o < 32; o <<= 1) {
        int n = __shfl_up_sync(0xffffffffu, inc, o);
        if (lane >= o) inc += n;
    }
    if (lane == 31) wsum[w] = inc;
    __syncthreads();
    if (t == 0) {
        int acc = 0;
#pragma unroll
        for (int i = 0; i < 8; i++) { int tmp = wsum[i]; wsum[i] = acc; acc += tmp; }
    }
    __syncthreads();
    int run = wsum[w] + inc - s;   // exclusive base for this thread
#pragma unroll
    for (int k = 0; k < 4; k++) {
        if (base + k < NN) g_rowptr[base + k] = run;
        run += c[k];
    }
    if (t == 255) g_bsum[blk] = wsum[7] + inc;  // block total
}

__global__ void csr_scan2_kernel() {
    __shared__ int wsum[8];
    int t = threadIdx.x;
    int lane = t & 31, w = t >> 5;
    int v = (t < NBLK) ? g_bsum[t] : 0;
    int inc = v;
#pragma unroll
    for (int o = 1; o < 32; o <<= 1) {
        int n = __shfl_up_sync(0xffffffffu, inc, o);
        if (lane >= o) inc += n;
    }
    if (lane == 31) wsum[w] = inc;
    __syncthreads();
    if (t == 0) {
        int acc = 0;
#pragma unroll
        for (int i = 0; i < 8; i++) { int tmp = wsum[i]; wsum[i] = acc; acc += tmp; }
    }
    __syncthreads();
    if (t < NBLK) g_boff[t] = wsum[w] + inc - v;
}

__global__ void csr_scan3_kernel() {
    int i = blockIdx.x * blockDim.x + threadIdx.x;
    if (i < NN) {
        int r = g_rowptr[i] + g_boff[i >> 10];
        g_rowptr[i] = r;
        g_cursor[i] = r;
    }
    if (i == 0) g_rowptr[NN] = EE;
}

__global__ void csr_fill_kernel(const int* __restrict__ src,
                                const int* __restrict__ dst) {
    int e = blockIdx.x * blockDim.x + threadIdx.x;
    if (e >= EE) return;
    int d = __ldg(dst + e);
    int pos = atomicAdd(&g_cursor[d], 1);
    g_colidx[pos] = __ldg(src + e);
}

// ---------------- gather: agg[d] = h[d] + sum_{s in nbrs(d)} h[s] ----------------
__global__ void gather_kernel() {
    int idx = blockIdx.x * blockDim.x + threadIdx.x;
    int node = idx >> 4;
    if (node >= NN) return;
    int c = idx & 15;
    int beg = __ldg(&g_rowptr[node]);
    int end = __ldg(&g_rowptr[node + 1]);
    float4 acc = *reinterpret_cast<const float4*>(g_h + (size_t)node * HID + c * 4);
    for (int e = beg; e < end; e++) {
        int s = __ldg(&g_colidx[e]);
        float4 v = *reinterpret_cast<const float4*>(g_h + (size_t)s * HID + c * 4);
        acc.x += v.x; acc.y += v.y; acc.z += v.z; acc.w += v.w;
    }
    *reinterpret_cast<float4*>(g_agg + (size_t)node * HID + c * 4) = acc;
}

__global__ void zero_pool_kernel() {
    int i = blockIdx.x * blockDim.x + threadIdx.x;
    if (i < GG * HID) g_pool[i] = 0.f;
    if (i < GG)       g_cnt[i]  = 0;
}

// ============================================================================
// GEMM micro-structure (R2, proven): tile 128 nodes x 64 outs, 256 threads.
// ============================================================================
#define XPAD 132

__global__ void __launch_bounds__(256, 4)
embed_kernel(const float* __restrict__ x,  const float* __restrict__ W,
             const float* __restrict__ bias,
             const float* __restrict__ bg, const float* __restrict__ bb,
             const float* __restrict__ bm, const float* __restrict__ bv,
             float* __restrict__ outh)
{
    __shared__ float xs[32][XPAD];
    __shared__ float Wsm[32][64];

    const int t  = threadIdx.x;
    const int og = t & 15;
    const int ng = t >> 4;
    const int n0 = blockIdx.x * 128;

    float acc[8][4];
#pragma unroll
    for (int i = 0; i < 8; i++)
#pragma unroll
        for (int j = 0; j < 4; j++) acc[i][j] = 0.f;

    for (int k0 = 0; k0 < INDIM; k0 += 32) {
#pragma unroll
        for (int r = 0; r < 4; r++) {
            int idx = r * 256 + t;
            int nn = idx >> 3, kq = idx & 7;
            int node = min(n0 + nn, NN - 1);
            float4 v = *reinterpret_cast<const float4*>(x + (size_t)node * INDIM + k0 + kq * 4);
            xs[kq * 4 + 0][nn] = v.x; xs[kq * 4 + 1][nn] = v.y;
            xs[kq * 4 + 2][nn] = v.z; xs[kq * 4 + 3][nn] = v.w;
        }
#pragma unroll
        for (int r = 0; r < 8; r++) {
            int i = r * 256 + t;
            int kk = i >> 6, oo = i & 63;
            Wsm[kk][oo] = W[(size_t)(k0 + kk) * HID + oo];
        }
        __syncthreads();
#pragma unroll 8
        for (int kk = 0; kk < 32; kk++) {
            float4 xa = *reinterpret_cast<const float4*>(&xs[kk][ng * 8]);
            float4 xb = *reinterpret_cast<const float4*>(&xs[kk][ng * 8 + 4]);
            float4 w  = *reinterpret_cast<const float4*>(&Wsm[kk][og * 4]);
            float xv[8] = {xa.x, xa.y, xa.z, xa.w, xb.x, xb.y, xb.z, xb.w};
            float wv[4] = {w.x, w.y, w.z, w.w};
#pragma unroll
            for (int i = 0; i < 8; i++)
#pragma unroll
                for (int j = 0; j < 4; j++) acc[i][j] += xv[i] * wv[j];
        }
        __syncthreads();
    }

    float s[4], sh[4];
#pragma unroll
    for (int j = 0; j < 4; j++) {
        int o = og * 4 + j;
        s[j]  = __ldg(bg + o) * rsqrtf(__ldg(bv + o) + BN_EPS);
        sh[j] = (__ldg(bias + o) - __ldg(bm + o)) * s[j] + __ldg(bb + o);
    }
#pragma unroll
    for (int i = 0; i < 8; i++) {
        int node = n0 + ng * 8 + i;
        if (node < NN) {
            float4 v;
            v.x = fmaxf(acc[i][0] * s[0] + sh[0], 0.f);
            v.y = fmaxf(acc[i][1] * s[1] + sh[1], 0.f);
            v.z = fmaxf(acc[i][2] * s[2] + sh[2], 0.f);
            v.w = fmaxf(acc[i][3] * s[3] + sh[3], 0.f);
            *reinterpret_cast<float4*>(outh + (size_t)node * HID + og * 4) = v;
        }
    }
}

__global__ void __launch_bounds__(256, 3)
fused_mlp(const float* __restrict__ in,
          const float* __restrict__ W1, const float* __restrict__ b1,
          const float* __restrict__ g1, const float* __restrict__ bb1,
          const float* __restrict__ m1, const float* __restrict__ v1,
          const float* __restrict__ W2, const float* __restrict__ b2,
          const float* __restrict__ g2, const float* __restrict__ bb2,
          const float* __restrict__ m2, const float* __restrict__ v2,
          float* __restrict__ outh)
{
    __shared__ float xs[32][XPAD];
    __shared__ float zs[64][XPAD];
    __shared__ float Wsm[32][64];

    const int t  = threadIdx.x;
    const int og = t & 15;
    const int ng = t >> 4;
    const int n0 = blockIdx.x * 128;

    float acc[8][4];
#pragma unroll
    for (int i = 0; i < 8; i++)
#pragma unroll
        for (int j = 0; j < 4; j++) acc[i][j] = 0.f;

    // GEMM1
    for (int k0 = 0; k0 < HID; k0 += 32) {
#pragma unroll
        for (int r = 0; r < 4; r++) {
            int idx = r * 256 + t;
            int nn = idx >> 3, kq = idx & 7;
            int node = min(n0 + nn, NN - 1);
            float4 v = *reinterpret_cast<const float4*>(in + (size_t)node * HID + k0 + kq * 4);
            xs[kq * 4 + 0][nn] = v.x; xs[kq * 4 + 1][nn] = v.y;
            xs[kq * 4 + 2][nn] = v.z; xs[kq * 4 + 3][nn] = v.w;
        }
#pragma unroll
        for (int r = 0; r < 8; r++) {
            int i = r * 256 + t;
            int kk = i >> 6, oo = i & 63;
            Wsm[kk][oo] = W1[(size_t)(k0 + kk) * HID + oo];
        }
        __syncthreads();
#pragma unroll 8
        for (int kk = 0; kk < 32; kk++) {
            float4 xa = *reinterpret_cast<const float4*>(&xs[kk][ng * 8]);
            float4 xb = *reinterpret_cast<const float4*>(&xs[kk][ng * 8 + 4]);
            float4 w  = *reinterpret_cast<const float4*>(&Wsm[kk][og * 4]);
            float xv[8] = {xa.x, xa.y, xa.z, xa.w, xb.x, xb.y, xb.z, xb.w};
            float wv[4] = {w.x, w.y, w.z, w.w};
#pragma unroll
            for (int i = 0; i < 8; i++)
#pragma unroll
                for (int j = 0; j < 4; j++) acc[i][j] += xv[i] * wv[j];
        }
        __syncthreads();
    }

    // epilogue1 -> zs [k][node]
    {
        float s[4], sh[4];
#pragma unroll
        for (int j = 0; j < 4; j++) {
            int o = og * 4 + j;
            s[j]  = __ldg(g1 + o) * rsqrtf(__ldg(v1 + o) + BN_EPS);
            sh[j] = (__ldg(b1 + o) - __ldg(m1 + o)) * s[j] + __ldg(bb1 + o);
        }
#pragma unroll
        for (int i = 0; i < 8; i++)
#pragma unroll
            for (int j = 0; j < 4; j++)
                zs[og * 4 + j][ng * 8 + i] = fmaxf(acc[i][j] * s[j] + sh[j], 0.f);
    }
    __syncthreads();

    // GEMM2
#pragma unroll
    for (int i = 0; i < 8; i++)
#pragma unroll
        for (int j = 0; j < 4; j++) acc[i][j] = 0.f;

    for (int c = 0; c < 2; c++) {
#pragma unroll
        for (int r = 0; r < 8; r++) {
            int i = r * 256 + t;
            int kk = i >> 6, oo = i & 63;
            Wsm[kk][oo] = W2[(size_t)(c * 32 + kk) * HID + oo];
        }
        __syncthreads();
#pragma unroll 8
        for (int kk = 0; kk < 32; kk++) {
            float4 xa = *reinterpret_cast<const float4*>(&zs[c * 32 + kk][ng * 8]);
            float4 xb = *reinterpret_cast<const float4*>(&zs[c * 32 + kk][ng * 8 + 4]);
            float4 w  = *reinterpret_cast<const float4*>(&Wsm[kk][og * 4]);
            float xv[8] = {xa.x, xa.y, xa.z, xa.w, xb.x, xb.y, xb.z, xb.w};
            float wv[4] = {w.x, w.y, w.z, w.w};
#pragma unroll
            for (int i = 0; i < 8; i++)
#pragma unroll
                for (int j = 0; j < 4; j++) acc[i][j] += xv[i] * wv[j];
        }
        __syncthreads();
    }

    float s[4], sh[4];
#pragma unroll
    for (int j = 0; j < 4; j++) {
        int o = og * 4 + j;
        s[j]  = __ldg(g2 + o) * rsqrtf(__ldg(v2 + o) + BN_EPS);
        sh[j] = (__ldg(b2 + o) - __ldg(m2 + o)) * s[j] + __ldg(bb2 + o);
    }
#pragma unroll
    for (int i = 0; i < 8; i++) {
        int node = n0 + ng * 8 + i;
        if (node < NN) {
            float4 v;
            v.x = fmaxf(acc[i][0] * s[0] + sh[0], 0.f);
            v.y = fmaxf(acc[i][1] * s[1] + sh[1], 0.f);
            v.z = fmaxf(acc[i][2] * s[2] + sh[2], 0.f);
            v.w = fmaxf(acc[i][3] * s[3] + sh[3], 0.f);
            *reinterpret_cast<float4*>(outh + (size_t)node * HID + og * 4) = v;
        }
    }
}

// ---------------- per-graph pooling ----------------
__global__ void pool_kernel(const int* __restrict__ batch)
{
    int idx = blockIdx.x * blockDim.x + threadIdx.x;
    int node = idx >> 4;
    if (node >= NN) return;
    int c = idx & 15;
    int b = __ldg(batch + node);
    const float4 v = *reinterpret_cast<const float4*>(g_h + (size_t)node * HID + c * 4);
    float4* p = reinterpret_cast<float4*>(g_pool + b * HID + c * 4);
    asm volatile("red.global.add.v4.f32 [%0], {%1,%2,%3,%4};"
                 :: "l"(p), "f"(v.x), "f"(v.y), "f"(v.z), "f"(v.w)
                 : "memory");
    if (c == 0) atomicAdd(&g_cnt[b], 1);
}

// ---------------- classifier head ----------------
__global__ void classifier_kernel(const float* __restrict__ W1, const float* __restrict__ b1,
                                  const float* __restrict__ W2, const float* __restrict__ b2,
                                  float* __restrict__ out)
{
    __shared__ float W1s[64 * 32];
    __shared__ float W2s[32 * NCLS];
    __shared__ float b1s[32];
    __shared__ float b2s[NCLS];
    int t = threadIdx.x;
    for (int i = t; i < 64 * 32;   i += 256) W1s[i] = W1[i];
    for (int i = t; i < 32 * NCLS; i += 256) W2s[i] = W2[i];
    if (t < 32)   b1s[t] = b1[t];
    if (t < NCLS) b2s[t] = b2[t];
    __syncthreads();

    int g = blockIdx.x * 256 + t;
    if (g >= GG) return;
    float inv = 1.f / fmaxf((float)g_cnt[g], 1.f);

    float h1[32];
#pragma unroll
    for (int j = 0; j < 32; j++) h1[j] = b1s[j];
    for (int k = 0; k < HID; k++) {
        float p = g_pool[g * HID + k] * inv;
#pragma unroll
        for (int j = 0; j < 32; j++) h1[j] += p * W1s[k * 32 + j];
    }
#pragma unroll
    for (int j = 0; j < 32; j++) h1[j] = fmaxf(h1[j], 0.f);

#pragma unroll
    for (int c = 0; c < NCLS; c++) {
        float o = b2s[c];
#pragma unroll
        for (int j = 0; j < 32; j++) o += h1[j] * W2s[j * NCLS + c];
        out[g * NCLS + c] = o;
    }
}

// ---------------- launcher ----------------
extern "C" void kernel_launch(void* const* d_in, const int* in_sizes, int n_in,
                              void* d_out, int out_size)
{
    const float* x      = (const float*)d_in[0];
    const int*   ei     = (const int*)  d_in[1];
    const int*   batch  = (const int*)  d_in[2];
    const float* emb_w  = (const float*)d_in[3];
    const float* emb_b  = (const float*)d_in[4];
    const float* ibn_g  = (const float*)d_in[5];
    const float* ibn_b  = (const float*)d_in[6];
    const float* ibn_m  = (const float*)d_in[7];
    const float* ibn_v  = (const float*)d_in[8];
    const float* fc1_w  = (const float*)d_in[9];
    const float* fc1_b  = (const float*)d_in[10];
    const float* mbn_g  = (const float*)d_in[11];
    const float* mbn_b  = (const float*)d_in[12];
    const float* mbn_m  = (const float*)d_in[13];
    const float* mbn_v  = (const float*)d_in[14];
    const float* fc2_w  = (const float*)d_in[15];
    const float* fc2_b  = (const float*)d_in[16];
    const float* obn_g  = (const float*)d_in[17];
    const float* obn_b  = (const float*)d_in[18];
    const float* obn_m  = (const float*)d_in[19];
    const float* obn_v  = (const float*)d_in[20];
    const float* cls1_w = (const float*)d_in[21];
    const float* cls1_b = (const float*)d_in[22];
    const float* cls2_w = (const float*)d_in[23];
    const float* cls2_b = (const float*)d_in[24];
    float* out = (float*)d_out;

    const int* src = ei;        // edge_index[0]
    const int* dst = ei + EE;   // edge_index[1]

    float *hp, *ap;
    cudaGetSymbolAddress((void**)&hp, g_h);
    cudaGetSymbolAddress((void**)&ap, g_agg);

    const int NB = (NN + 127) / 128;

    // ---- build CSR of incoming edges (structure reused by all 3 layers) ----
    csr_zero_kernel <<<(NN + 255) / 256, 256>>>();
    csr_hist_kernel <<<(EE + 255) / 256, 256>>>(dst);
    csr_scan1_kernel<<<NBLK, 256>>>();
    csr_scan2_kernel<<<1, 256>>>();
    csr_scan3_kernel<<<(NN + 255) / 256, 256>>>();
    csr_fill_kernel <<<(EE + 255) / 256, 256>>>(src, dst);

    // input embedding -> BN -> relu -> h
    embed_kernel<<<NB, 256>>>(x, emb_w, emb_b, ibn_g, ibn_b, ibn_m, ibn_v, hp);

    for (int l = 0; l < LAYERS; l++) {
        gather_kernel<<<(NN * 16 + 255) / 256, 256>>>();
        fused_mlp<<<NB, 256>>>(
            ap,
            fc1_w + (size_t)l * HID * HID, fc1_b + l * HID,
            mbn_g + l * HID, mbn_b + l * HID, mbn_m + l * HID, mbn_v + l * HID,
            fc2_w + (size_t)l * HID * HID, fc2_b + l * HID,
            obn_g + l * HID, obn_b + l * HID, obn_m + l * HID, obn_v + l * HID,
            hp);
    }

    zero_pool_kernel<<<(GG * HID + 255) / 256, 256>>>();
    pool_kernel<<<(NN * 16 + 255) / 256, 256>>>(batch);
    classifier_kernel<<<(GG + 255) / 256, 256>>>(cls1_w, cls1_b, cls2_w, cls2_b, out);
}

// round 5
// speedup vs baseline: 1.6687x; 1.0405x over previous
#include <cuda_runtime.h>
#include <cstdint>

#define NN      200000
#define EE      1200000
#define INDIM   128
#define HID     64
#define GG      1024
#define NCLS    6
#define LAYERS  3
#define BN_EPS  1e-5f
#define NBLK    ((NN + 1023) / 1024)   // 196 scan blocks

// ---------------- scratch (static device globals; no allocation) ----------------
__device__ float g_h  [(size_t)NN * HID];
__device__ float g_agg[(size_t)NN * HID];
__device__ float g_pool[GG * HID];
__device__ int   g_cnt [GG];
// CSR structures (rebuilt every launch; deterministic given inputs)
__device__ int   g_rowptr[NN + 1];
__device__ int   g_cursor[NN];
__device__ int   g_colidx[EE];
__device__ int   g_bsum[256];
__device__ int   g_boff[256];

// ---------------- packed f32x2 helpers (bit-exact dual fp32 FMA) ----------------
__device__ __forceinline__ unsigned long long ffma2(unsigned long long a,
                                                    unsigned long long b,
                                                    unsigned long long c) {
    unsigned long long d;
    asm("fma.rn.f32x2 %0, %1, %2, %3;" : "=l"(d) : "l"(a), "l"(b), "l"(c));
    return d;
}
__device__ __forceinline__ unsigned long long dup2(float w) {
    unsigned long long d;
    asm("mov.b64 %0, {%1, %1};" : "=l"(d) : "r"(__float_as_uint(w)));
    return d;
}
__device__ __forceinline__ void unpack2(unsigned long long v, float& lo, float& hi) {
    unsigned int a, b;
    asm("mov.b64 {%0, %1}, %2;" : "=r"(a), "=r"(b) : "l"(v));
    lo = __uint_as_float(a);
    hi = __uint_as_float(b);
}

// ================= CSR build =================
__global__ void csr_zero_kernel() {
    int i = blockIdx.x * blockDim.x + threadIdx.x;
    if (i < NN) g_cursor[i] = 0;
}

__global__ void csr_hist_kernel(const int* __restrict__ dst) {
    int e = blockIdx.x * blockDim.x + threadIdx.x;
    if (e < EE) atomicAdd(&g_cursor[__ldg(dst + e)], 1);
}

__global__ void csr_scan1_kernel() {
    __shared__ int wsum[8];
    int t = threadIdx.x, blk = blockIdx.x;
    int lane = t & 31, w = t >> 5;
    int base = blk * 1024 + t * 4;
    int c[4], s = 0;
#pragma unroll
    for (int k = 0; k < 4; k++) {
        c[k] = (base + k < NN) ? g_cursor[base + k] : 0;
        s += c[k];
    }
    int inc = s;
#pragma unroll
    for (int o = 1; o < 32; o <<= 1) {
        int n = __shfl_up_sync(0xffffffffu, inc, o);
        if (lane >= o) inc += n;
    }
    if (lane == 31) wsum[w] = inc;
    __syncthreads();
    if (t == 0) {
        int acc = 0;
#pragma unroll
        for (int i = 0; i < 8; i++) { int tmp = wsum[i]; wsum[i] = acc; acc += tmp; }
    }
    __syncthreads();
    int run = wsum[w] + inc - s;
#pragma unroll
    for (int k = 0; k < 4; k++) {
        if (base + k < NN) g_rowptr[base + k] = run;
        run += c[k];
    }
    if (t == 255) g_bsum[blk] = wsum[7] + inc;
}

__global__ void csr_scan2_kernel() {
    __shared__ int wsum[8];
    int t = threadIdx.x;
    int lane = t & 31, w = t >> 5;
    int v = (t < NBLK) ? g_bsum[t] : 0;
    int inc = v;
#pragma unroll
    for (int o = 1; o < 32; o <<= 1) {
        int n = __shfl_up_sync(0xffffffffu, inc, o);
        if (lane >= o) inc += n;
    }
    if (lane == 31) wsum[w] = inc;
    __syncthreads();
    if (t == 0) {
        int acc = 0;
#pragma unroll
        for (int i = 0; i < 8; i++) { int tmp = wsum[i]; wsum[i] = acc; acc += tmp; }
    }
    __syncthreads();
    if (t < NBLK) g_boff[t] = wsum[w] + inc - v;
}

__global__ void csr_scan3_kernel() {
    int i = blockIdx.x * blockDim.x + threadIdx.x;
    if (i < NN) {
        int r = g_rowptr[i] + g_boff[i >> 10];
        g_rowptr[i] = r;
        g_cursor[i] = r;
    }
    if (i == 0) g_rowptr[NN] = EE;
}

__global__ void csr_fill_kernel(const int* __restrict__ src,
                                const int* __restrict__ dst) {
    int e = blockIdx.x * blockDim.x + threadIdx.x;
    if (e >= EE) return;
    int d = __ldg(dst + e);
    int pos = atomicAdd(&g_cursor[d], 1);
    g_colidx[pos] = __ldg(src + e);
}

// ---------------- gather: agg[d] = h[d] + sum_{s in nbrs(d)} h[s] ----------------
__global__ void gather_kernel() {
    int idx = blockIdx.x * blockDim.x + threadIdx.x;
    int node = idx >> 4;
    if (node >= NN) return;
    int c = idx & 15;
    int beg = __ldg(&g_rowptr[node]);
    int end = __ldg(&g_rowptr[node + 1]);
    float4 acc = *reinterpret_cast<const float4*>(g_h + (size_t)node * HID + c * 4);
    for (int e = beg; e < end; e++) {
        int s = __ldg(&g_colidx[e]);
        float4 v = *reinterpret_cast<const float4*>(g_h + (size_t)s * HID + c * 4);
        acc.x += v.x; acc.y += v.y; acc.z += v.z; acc.w += v.w;
    }
    *reinterpret_cast<float4*>(g_agg + (size_t)node * HID + c * 4) = acc;
}

__global__ void zero_pool_kernel() {
    int i = blockIdx.x * blockDim.x + threadIdx.x;
    if (i < GG * HID) g_pool[i] = 0.f;
    if (i < GG)       g_cnt[i]  = 0;
}

// ============================================================================
// GEMM micro-structure: tile 128 nodes x 64 outs, 256 threads.
// og = t&15 -> outs og*4+j ; ng = t>>4 -> node-pairs (ng*8 + 2i, +2i+1), i<4.
// Accumulators packed f32x2 over node pairs: 16 FFMA2 + 4 MOV per kk.
// ============================================================================
#define XPAD 132

__global__ void __launch_bounds__(256, 4)
embed_kernel(const float* __restrict__ x,  const float* __restrict__ W,
             const float* __restrict__ bias,
             const float* __restrict__ bg, const float* __restrict__ bb,
             const float* __restrict__ bm, const float* __restrict__ bv,
             float* __restrict__ outh)
{
    __shared__ float xs[32][XPAD];
    __shared__ float Wsm[32][64];

    const int t  = threadIdx.x;
    const int og = t & 15;
    const int ng = t >> 4;
    const int n0 = blockIdx.x * 128;

    unsigned long long acc[4][4];
#pragma unroll
    for (int i = 0; i < 4; i++)
#pragma unroll
        for (int j = 0; j < 4; j++) acc[i][j] = 0ULL;

    for (int k0 = 0; k0 < INDIM; k0 += 32) {
#pragma unroll
        for (int r = 0; r < 4; r++) {
            int idx = r * 256 + t;
            int nn = idx >> 3, kq = idx & 7;
            int node = min(n0 + nn, NN - 1);
            float4 v = *reinterpret_cast<const float4*>(x + (size_t)node * INDIM + k0 + kq * 4);
            xs[kq * 4 + 0][nn] = v.x; xs[kq * 4 + 1][nn] = v.y;
            xs[kq * 4 + 2][nn] = v.z; xs[kq * 4 + 3][nn] = v.w;
        }
#pragma unroll
        for (int r = 0; r < 8; r++) {
            int i = r * 256 + t;
            int kk = i >> 6, oo = i & 63;
            Wsm[kk][oo] = W[(size_t)(k0 + kk) * HID + oo];
        }
        __syncthreads();
#pragma unroll 8
        for (int kk = 0; kk < 32; kk++) {
            const ulonglong2* xp = reinterpret_cast<const ulonglong2*>(&xs[kk][ng * 8]);
            ulonglong2 xA = xp[0], xB = xp[1];
            unsigned long long xv[4] = {xA.x, xA.y, xB.x, xB.y};
            float4 wf = *reinterpret_cast<const float4*>(&Wsm[kk][og * 4]);
            unsigned long long wv[4] = {dup2(wf.x), dup2(wf.y), dup2(wf.z), dup2(wf.w)};
#pragma unroll
            for (int i = 0; i < 4; i++)
#pragma unroll
                for (int j = 0; j < 4; j++) acc[i][j] = ffma2(xv[i], wv[j], acc[i][j]);
        }
        __syncthreads();
    }

    float s[4], sh[4];
#pragma unroll
    for (int j = 0; j < 4; j++) {
        int o = og * 4 + j;
        s[j]  = __ldg(bg + o) * rsqrtf(__ldg(bv + o) + BN_EPS);
        sh[j] = (__ldg(bias + o) - __ldg(bm + o)) * s[j] + __ldg(bb + o);
    }
#pragma unroll
    for (int i = 0; i < 4; i++) {
        float f0[4], f1[4];
#pragma unroll
        for (int j = 0; j < 4; j++) unpack2(acc[i][j], f0[j], f1[j]);
        int node0 = n0 + ng * 8 + 2 * i;
        if (node0 < NN) {
            float4 v;
            v.x = fmaxf(f0[0] * s[0] + sh[0], 0.f);
            v.y = fmaxf(f0[1] * s[1] + sh[1], 0.f);
            v.z = fmaxf(f0[2] * s[2] + sh[2], 0.f);
            v.w = fmaxf(f0[3] * s[3] + sh[3], 0.f);
            *reinterpret_cast<float4*>(outh + (size_t)node0 * HID + og * 4) = v;
        }
        if (node0 + 1 < NN) {
            float4 v;
            v.x = fmaxf(f1[0] * s[0] + sh[0], 0.f);
            v.y = fmaxf(f1[1] * s[1] + sh[1], 0.f);
            v.z = fmaxf(f1[2] * s[2] + sh[2], 0.f);
            v.w = fmaxf(f1[3] * s[3] + sh[3], 0.f);
            *reinterpret_cast<float4*>(outh + (size_t)(node0 + 1) * HID + og * 4) = v;
        }
    }
}

__global__ void __launch_bounds__(256, 3)
fused_mlp(const float* __restrict__ in,
          const float* __restrict__ W1, const float* __restrict__ b1,
          const float* __restrict__ g1, const float* __restrict__ bb1,
          const float* __restrict__ m1, const float* __restrict__ v1,
          const float* __restrict__ W2, const float* __restrict__ b2,
          const float* __restrict__ g2, const float* __restrict__ bb2,
          const float* __restrict__ m2, const float* __restrict__ v2,
          float* __restrict__ outh)
{
    __shared__ float xs[32][XPAD];
    __shared__ float zs[64][XPAD];
    __shared__ float Wsm[32][64];

    const int t  = threadIdx.x;
    const int og = t & 15;
    const int ng = t >> 4;
    const int n0 = blockIdx.x * 128;

    unsigned long long acc[4][4];
#pragma unroll
    for (int i = 0; i < 4; i++)
#pragma unroll
        for (int j = 0; j < 4; j++) acc[i][j] = 0ULL;

    // ---------- GEMM1 ----------
    for (int k0 = 0; k0 < HID; k0 += 32) {
#pragma unroll
        for (int r = 0; r < 4; r++) {
            int idx = r * 256 + t;
            int nn = idx >> 3, kq = idx & 7;
            int node = min(n0 + nn, NN - 1);
            float4 v = *reinterpret_cast<const float4*>(in + (size_t)node * HID + k0 + kq * 4);
            xs[kq * 4 + 0][nn] = v.x; xs[kq * 4 + 1][nn] = v.y;
            xs[kq * 4 + 2][nn] = v.z; xs[kq * 4 + 3][nn] = v.w;
        }
#pragma unroll
        for (int r = 0; r < 8; r++) {
            int i = r * 256 + t;
            int kk = i >> 6, oo = i & 63;
            Wsm[kk][oo] = W1[(size_t)(k0 + kk) * HID + oo];
        }
        __syncthreads();
#pragma unroll 8
        for (int kk = 0; kk < 32; kk++) {
            const ulonglong2* xp = reinterpret_cast<const ulonglong2*>(&xs[kk][ng * 8]);
            ulonglong2 xA = xp[0], xB = xp[1];
            unsigned long long xv[4] = {xA.x, xA.y, xB.x, xB.y};
            float4 wf = *reinterpret_cast<const float4*>(&Wsm[kk][og * 4]);
            unsigned long long wv[4] = {dup2(wf.x), dup2(wf.y), dup2(wf.z), dup2(wf.w)};
#pragma unroll
            for (int i = 0; i < 4; i++)
#pragma unroll
                for (int j = 0; j < 4; j++) acc[i][j] = ffma2(xv[i], wv[j], acc[i][j]);
        }
        __syncthreads();
    }

    // epilogue1: BN + relu -> zs [k][node]
    {
        float s[4], sh[4];
#pragma unroll
        for (int j = 0; j < 4; j++) {
            int o = og * 4 + j;
            s[j]  = __ldg(g1 + o) * rsqrtf(__ldg(v1 + o) + BN_EPS);
            sh[j] = (__ldg(b1 + o) - __ldg(m1 + o)) * s[j] + __ldg(bb1 + o);
        }
#pragma unroll
        for (int i = 0; i < 4; i++) {
            float f0[4], f1[4];
#pragma unroll
            for (int j = 0; j < 4; j++) unpack2(acc[i][j], f0[j], f1[j]);
#pragma unroll
            for (int j = 0; j < 4; j++) {
                zs[og * 4 + j][ng * 8 + 2 * i]     = fmaxf(f0[j] * s[j] + sh[j], 0.f);
                zs[og * 4 + j][ng * 8 + 2 * i + 1] = fmaxf(f1[j] * s[j] + sh[j], 0.f);
            }
        }
    }
    __syncthreads();

    // ---------- GEMM2 ----------
#pragma unroll
    for (int i = 0; i < 4; i++)
#pragma unroll
        for (int j = 0; j < 4; j++) acc[i][j] = 0ULL;

    for (int c = 0; c < 2; c++) {
#pragma unroll
        for (int r = 0; r < 8; r++) {
            int i = r * 256 + t;
            int kk = i >> 6, oo = i & 63;
            Wsm[kk][oo] = W2[(size_t)(c * 32 + kk) * HID + oo];
        }
        __syncthreads();
#pragma unroll 8
        for (int kk = 0; kk < 32; kk++) {
            const ulonglong2* xp = reinterpret_cast<const ulonglong2*>(&zs[c * 32 + kk][ng * 8]);
            ulonglong2 xA = xp[0], xB = xp[1];
            unsigned long long xv[4] = {xA.x, xA.y, xB.x, xB.y};
            float4 wf = *reinterpret_cast<const float4*>(&Wsm[kk][og * 4]);
            unsigned long long wv[4] = {dup2(wf.x), dup2(wf.y), dup2(wf.z), dup2(wf.w)};
#pragma unroll
            for (int i = 0; i < 4; i++)
#pragma unroll
                for (int j = 0; j < 4; j++) acc[i][j] = ffma2(xv[i], wv[j], acc[i][j]);
        }
        __syncthreads();
    }

    float s[4], sh[4];
#pragma unroll
    for (int j = 0; j < 4; j++) {
        int o = og * 4 + j;
        s[j]  = __ldg(g2 + o) * rsqrtf(__ldg(v2 + o) + BN_EPS);
        sh[j] = (__ldg(b2 + o) - __ldg(m2 + o)) * s[j] + __ldg(bb2 + o);
    }
#pragma unroll
    for (int i = 0; i < 4; i++) {
        float f0[4], f1[4];
#pragma unroll
        for (int j = 0; j < 4; j++) unpack2(acc[i][j], f0[j], f1[j]);
        int node0 = n0 + ng * 8 + 2 * i;
        if (node0 < NN) {
            float4 v;
            v.x = fmaxf(f0[0] * s[0] + sh[0], 0.f);
            v.y = fmaxf(f0[1] * s[1] + sh[1], 0.f);
            v.z = fmaxf(f0[2] * s[2] + sh[2], 0.f);
            v.w = fmaxf(f0[3] * s[3] + sh[3], 0.f);
            *reinterpret_cast<float4*>(outh + (size_t)node0 * HID + og * 4) = v;
        }
        if (node0 + 1 < NN) {
            float4 v;
            v.x = fmaxf(f1[0] * s[0] + sh[0], 0.f);
            v.y = fmaxf(f1[1] * s[1] + sh[1], 0.f);
            v.z = fmaxf(f1[2] * s[2] + sh[2], 0.f);
            v.w = fmaxf(f1[3] * s[3] + sh[3], 0.f);
            *reinterpret_cast<float4*>(outh + (size_t)(node0 + 1) * HID + og * 4) = v;
        }
    }
}

// ---------------- per-graph pooling ----------------
__global__ void pool_kernel(const int* __restrict__ batch)
{
    int idx = blockIdx.x * blockDim.x + threadIdx.x;
    int node = idx >> 4;
    if (node >= NN) return;
    int c = idx & 15;
    int b = __ldg(batch + node);
    const float4 v = *reinterpret_cast<const float4*>(g_h + (size_t)node * HID + c * 4);
    float4* p = reinterpret_cast<float4*>(g_pool + b * HID + c * 4);
    asm volatile("red.global.add.v4.f32 [%0], {%1,%2,%3,%4};"
                 :: "l"(p), "f"(v.x), "f"(v.y), "f"(v.z), "f"(v.w)
                 : "memory");
    if (c == 0) atomicAdd(&g_cnt[b], 1);
}

// ---------------- classifier head ----------------
__global__ void classifier_kernel(const float* __restrict__ W1, const float* __restrict__ b1,
                                  const float* __restrict__ W2, const float* __restrict__ b2,
                                  float* __restrict__ out)
{
    __shared__ float W1s[64 * 32];
    __shared__ float W2s[32 * NCLS];
    __shared__ float b1s[32];
    __shared__ float b2s[NCLS];
    int t = threadIdx.x;
    for (int i = t; i < 64 * 32;   i += 256) W1s[i] = W1[i];
    for (int i = t; i < 32 * NCLS; i += 256) W2s[i] = W2[i];
    if (t < 32)   b1s[t] = b1[t];
    if (t < NCLS) b2s[t] = b2[t];
    __syncthreads();

    int g = blockIdx.x * 256 + t;
    if (g >= GG) return;
    float inv = 1.f / fmaxf((float)g_cnt[g], 1.f);

    float h1[32];
#pragma unroll
    for (int j = 0; j < 32; j++) h1[j] = b1s[j];
    for (int k = 0; k < HID; k++) {
        float p = g_pool[g * HID + k] * inv;
#pragma unroll
        for (int j = 0; j < 32; j++) h1[j] += p * W1s[k * 32 + j];
    }
#pragma unroll
    for (int j = 0; j < 32; j++) h1[j] = fmaxf(h1[j], 0.f);

#pragma unroll
    for (int c = 0; c < NCLS; c++) {
        float o = b2s[c];
#pragma unroll
        for (int j = 0; j < 32; j++) o += h1[j] * W2s[j * NCLS + c];
        out[g * NCLS + c] = o;
    }
}

// ---------------- launcher ----------------
extern "C" void kernel_launch(void* const* d_in, const int* in_sizes, int n_in,
                              void* d_out, int out_size)
{
    const float* x      = (const float*)d_in[0];
    const int*   ei     = (const int*)  d_in[1];
    const int*   batch  = (const int*)  d_in[2];
    const float* emb_w  = (const float*)d_in[3];
    const float* emb_b  = (const float*)d_in[4];
    const float* ibn_g  = (const float*)d_in[5];
    const float* ibn_b  = (const float*)d_in[6];
    const float* ibn_m  = (const float*)d_in[7];
    const float* ibn_v  = (const float*)d_in[8];
    const float* fc1_w  = (const float*)d_in[9];
    const float* fc1_b  = (const float*)d_in[10];
    const float* mbn_g  = (const float*)d_in[11];
    const float* mbn_b  = (const float*)d_in[12];
    const float* mbn_m  = (const float*)d_in[13];
    const float* mbn_v  = (const float*)d_in[14];
    const float* fc2_w  = (const float*)d_in[15];
    const float* fc2_b  = (const float*)d_in[16];
    const float* obn_g  = (const float*)d_in[17];
    const float* obn_b  = (const float*)d_in[18];
    const float* obn_m  = (const float*)d_in[19];
    const float* obn_v  = (const float*)d_in[20];
    const float* cls1_w = (const float*)d_in[21];
    const float* cls1_b = (const float*)d_in[22];
    const float* cls2_w = (const float*)d_in[23];
    const float* cls2_b = (const float*)d_in[24];
    float* out = (float*)d_out;

    const int* src = ei;        // edge_index[0]
    const int* dst = ei + EE;   // edge_index[1]

    float *hp, *ap;
    cudaGetSymbolAddress((void**)&hp, g_h);
    cudaGetSymbolAddress((void**)&ap, g_agg);

    const int NB = (NN + 127) / 128;

    // ---- build CSR of incoming edges (reused by all 3 layers) ----
    csr_zero_kernel <<<(NN + 255) / 256, 256>>>();
    csr_hist_kernel <<<(EE + 255) / 256, 256>>>(dst);
    csr_scan1_kernel<<<NBLK, 256>>>();
    csr_scan2_kernel<<<1, 256>>>();
    csr_scan3_kernel<<<(NN + 255) / 256, 256>>>();
    csr_fill_kernel <<<(EE + 255) / 256, 256>>>(src, dst);

    // input embedding -> BN -> relu -> h
    embed_kernel<<<NB, 256>>>(x, emb_w, emb_b, ibn_g, ibn_b, ibn_m, ibn_v, hp);

    for (int l = 0; l < LAYERS; l++) {
        gather_kernel<<<(NN * 16 + 255) / 256, 256>>>();
        fused_mlp<<<NB, 256>>>(
            ap,
            fc1_w + (size_t)l * HID * HID, fc1_b + l * HID,
            mbn_g + l * HID, mbn_b + l * HID, mbn_m + l * HID, mbn_v + l * HID,
            fc2_w + (size_t)l * HID * HID, fc2_b + l * HID,
            obn_g + l * HID, obn_b + l * HID, obn_m + l * HID, obn_v + l * HID,
            hp);
    }

    zero_pool_kernel<<<(GG * HID + 255) / 256, 256>>>();
    pool_kernel<<<(NN * 16 + 255) / 256, 256>>>(batch);
    classifier_kernel<<<(GG + 255) / 256, 256>>>(cls1_w, cls1_b, cls2_w, cls2_b, out);
}